// round 10
// baseline (speedup 1.0000x reference)
#include <cuda_runtime.h>
#include <cstdint>
#include <cstddef>

#define BB 512
#define TT 512
#define LBL 126
#define NS 128            // L + 2
#define STRIDE 132        // padded row stride for conflict-free LDS.128
#define FILLF (-1000.0f)
#define LOG2E 1.4426950408889634f
#define LN2   0.6931471805599453f
#define NTHR 256          // 2 groups of 128; each thread = 1 column x 2 batches

__device__ float g_V[NS * NS];    // g_V[j*NS+i] = 2^(trans[i][j]*log2e); row L := 1.0 (U trick)
__device__ float g_total[BB];
__device__ float g_real[BB];

__device__ __forceinline__ float ex2f(float x) {
    float y; asm("ex2.approx.ftz.f32 %0, %1;" : "=f"(y) : "f"(x)); return y;
}
__device__ __forceinline__ float lg2f(float x) {
    float y; asm("lg2.approx.ftz.f32 %0, %1;" : "=f"(y) : "f"(x)); return y;
}
__device__ __forceinline__ float rcpf(float x) {
    float y; asm("rcp.approx.ftz.f32 %0, %1;" : "=f"(y) : "f"(x)); return y;
}

// Packed MAC: p = u2*v2 (f32x2), P2 += p (f32x2), m0/m1 = max with p's halves.
__device__ __forceinline__ void mac2(uint64_t u2, uint64_t v2,
                                     uint64_t& P2, float& m0, float& m1) {
    asm("{\n\t"
        ".reg .b64 p;\n\t"
        ".reg .f32 lo, hi;\n\t"
        "mul.rn.f32x2 p, %3, %4;\n\t"
        "mov.b64 {lo, hi}, p;\n\t"
        "add.rn.f32x2 %0, %0, p;\n\t"
        "max.f32 %1, %1, lo;\n\t"
        "max.f32 %2, %2, hi;\n\t"
        "}"
        : "+l"(P2), "+f"(m0), "+f"(m1)
        : "l"(u2), "l"(v2));
}

__device__ __forceinline__ float2 u64f2(uint64_t x) {
    float2 r; asm("mov.b64 {%0,%1}, %2;" : "=f"(r.x), "=f"(r.y) : "l"(x)); return r;
}

// Precompute V (transposed, exponentiated, log2 domain). Row LBL of V^T is 1.0:
// thread L's inner loop then yields Ps_L = sum_i u_i and mp_L = max_i u_i,
// exactly what column L needs (its true transitions are all FILL -> 0).
__global__ void prep_kernel(const float* __restrict__ trans) {
    int o = blockIdx.x * blockDim.x + threadIdx.x;   // o = j*NS + i
    if (o < NS * NS) {
        int j = o >> 7, i = o & 127;
        g_V[o] = (j == LBL) ? 1.0f : ex2f(trans[i * NS + j] * LOG2E);
    }
}

// Main forward scan. 128 CTAs x 256 threads; group g (128 thr) handles
// batches (bid*4 + 2g, bid*4 + 2g + 1); thread j owns column j of both.
// u_j = 2^(pre_j - A) in smem (double-buffered). Normalizer Cn = reference
// column 0's lm from the PREVIOUS step (lag-1 -> stable; written to smem
// before the barrier, read after, no reduction on the critical path).
// The group sum S = sum_j s_j is reduced AFTER the barrier and consumed one
// step late: acc += lg2(S) + Cn_used is timing-free scalar bookkeeping.
__global__ void __launch_bounds__(NTHR, 1) main_kernel(const float* __restrict__ emis) {
    extern __shared__ float sm[];
    const int tid  = threadIdx.x;
    const int g    = tid >> 7;
    const int j    = tid & 127;
    const int w    = (tid >> 5) & 3;
    const int lane = tid & 31;

    float*  VT   = sm;                                  // NS*STRIDE
    float*  ubuf = sm + NS * STRIDE + g * 512;          // 2 bufs x (uA[128],uB[128])
    float2* red  = reinterpret_cast<float2*>(sm + NS * STRIDE + 1024) + g * 8;  // 2 slots x 4
    float2* mref = reinterpret_cast<float2*>(sm + NS * STRIDE + 1024 + 32) + g * 2;  // 2 slots

    for (int k = tid; k < NS * NS; k += NTHR)
        VT[(k >> 7) * STRIDE + (k & 127)] = g_V[k];

    const int bA = blockIdx.x * 4 + g * 2;
    const int bB = bA + 1;
    const float CF = FILLF * LOG2E;
    const int barid = g + 1;

    // init u (buffer 0): indicator of start state L
    ubuf[j]       = (j == LBL) ? 1.0f : 0.0f;   // uA
    ubuf[128 + j] = (j == LBL) ? 1.0f : 0.0f;   // uB

    float accA = 0.0f, accB = 0.0f;
    float CnA = 0.0f, CnB = 0.0f;         // normalizer used at current step's u-store
    float CnPrevA = 0.0f, CnPrevB = 0.0f; // normalizer used one step earlier

    const float* eA = emis + (size_t)bA * TT * LBL;
    const float* eB = emis + (size_t)bB * TT * LBL;
    float rawA = 0.0f, rawB = 0.0f;
    if (j < LBL) { rawA = eA[j]; rawB = eB[j]; }
    asm volatile("bar.sync %0, 128;" :: "r"(barid) : "memory");

    const float* vrow = VT + j * STRIDE;
    const float* ucur = ubuf;           // reads buf[t&1]
    float*       unxt = ubuf + 256;     // writes buf[(t+1)&1]
    const bool isL = (j == LBL);

    for (int t = 0; t <= TT; ++t) {
        float obsA, obsB;
        if (t < TT) {
            obsA = (j < LBL) ? rawA * LOG2E : CF;
            obsB = (j < LBL) ? rawB * LOG2E : CF;
        } else {
            obsA = (j == LBL + 1) ? 0.0f : CF;
            obsB = obsA;
        }
        if (t + 1 < TT && j < LBL) {          // prefetch next emission row
            rawA = eA[(size_t)(t + 1) * LBL + j];
            rawB = eB[(size_t)(t + 1) * LBL + j];
        }

        // Inner matvec+max: p = u_i * V_ij ; mp = max p ; Ps = sum p.
        const float* uA = ucur;
        const float* uB = ucur + 128;
        uint64_t PA0 = 0, PA1 = 0, PB0 = 0, PB1 = 0;
        float mA0 = 0.f, mA1 = 0.f, mA2 = 0.f, mA3 = 0.f;
        float mB0 = 0.f, mB1 = 0.f, mB2 = 0.f, mB3 = 0.f;
        #pragma unroll 8
        for (int i = 0; i < NS; i += 4) {
            ulonglong2 v2 = *reinterpret_cast<const ulonglong2*>(vrow + i);
            ulonglong2 a2 = *reinterpret_cast<const ulonglong2*>(uA + i);  // broadcast
            ulonglong2 b2 = *reinterpret_cast<const ulonglong2*>(uB + i);  // broadcast
            mac2(a2.x, v2.x, PA0, mA0, mA1);
            mac2(a2.y, v2.y, PA1, mA2, mA3);
            mac2(b2.x, v2.x, PB0, mB0, mB1);
            mac2(b2.y, v2.y, PB1, mB2, mB3);
        }
        float2 fA0 = u64f2(PA0), fA1 = u64f2(PA1);
        float2 fB0 = u64f2(PB0), fB1 = u64f2(PB1);
        const float PsA = (fA0.x + fA0.y) + (fA1.x + fA1.y);
        const float PsB = (fB0.x + fB0.y) + (fB1.x + fB1.y);
        const float mpA = fmaxf(fmaxf(mA0, mA1), fmaxf(mA2, mA3));
        const float mpB = fmaxf(fmaxf(mB0, mB1), fmaxf(mB2, mB3));

        // Column L uses the identical formula (mp_L = max u, Ps_L = sum u).
        const float lgA = lg2f(mpA);
        const float lgB = lg2f(mpB);
        const float lmA = isL ? (lgA + CF) : lgA;
        const float lmB = isL ? (lgB + CF) : lgB;
        const float sA  = PsA * rcpf(mpA);
        const float sB  = PsB * rcpf(mpB);
        const float dA  = obsA + lmA;   // pre_new_j = A + lg2S + Cn + (d_j - Cn)
        const float dB  = obsB + lmB;

        // Next u with lag-1 reference-column normalizer (already in registers).
        unxt[j]       = ex2f(dA - CnA);
        unxt[128 + j] = ex2f(dB - CnB);

        // Reference column 0 publishes its lm as next step's normalizer.
        if (j == 0) mref[t & 1] = make_float2(lgA, lgB);

        asm volatile("bar.sync %0, 128;" :: "r"(barid) : "memory");

        // ---- Deferred sum-reduction (latency hidden behind next step) ----
        float rsA = sA, rsB = sB;
        #pragma unroll
        for (int o = 16; o > 0; o >>= 1) {
            rsA += __shfl_xor_sync(0xffffffffu, rsA, o);
            rsB += __shfl_xor_sync(0xffffffffu, rsB, o);
        }
        if (lane == 0) red[(t & 1) * 4 + w] = make_float2(rsA, rsB);

        // Next step's normalizer (STS drained by the bar above).
        const float2 cn = mref[t & 1];

        // Consume step t-1's S (slot races are two bars apart -> safe).
        if (t > 0) {
            const float2* pbuf = red + ((t - 1) & 1) * 4;
            const float2 q0 = pbuf[0], q1 = pbuf[1], q2 = pbuf[2], q3 = pbuf[3];
            accA += lg2f((q0.x + q1.x) + (q2.x + q3.x)) + CnPrevA;
            accB += lg2f((q0.y + q1.y) + (q2.y + q3.y)) + CnPrevB;
        }
        CnPrevA = CnA;  CnA = cn.x;
        CnPrevB = CnB;  CnB = cn.y;

        const float* tmp = ucur; ucur = unxt; unxt = const_cast<float*>(tmp);
    }

    // Drain step TT's reduction.
    asm volatile("bar.sync %0, 128;" :: "r"(barid) : "memory");
    {
        const float2* pbuf = red + (TT & 1) * 4;
        const float2 q0 = pbuf[0], q1 = pbuf[1], q2 = pbuf[2], q3 = pbuf[3];
        accA += lg2f((q0.x + q1.x) + (q2.x + q3.x)) + CnPrevA;
        accB += lg2f((q0.y + q1.y) + (q2.y + q3.y)) + CnPrevB;
    }

    // Final per-batch logsumexp: total = acc + lg2(sum_j u_j).
    float ruA = ucur[j], ruB = ucur[128 + j];
    #pragma unroll
    for (int o = 16; o > 0; o >>= 1) {
        ruA += __shfl_xor_sync(0xffffffffu, ruA, o);
        ruB += __shfl_xor_sync(0xffffffffu, ruB, o);
    }
    if (lane == 0) red[((TT + 1) & 1) * 4 + w] = make_float2(ruA, ruB);
    asm volatile("bar.sync %0, 128;" :: "r"(barid) : "memory");
    if (j == 0) {
        const float2* pbuf = red + ((TT + 1) & 1) * 4;
        const float2 q0 = pbuf[0], q1 = pbuf[1], q2 = pbuf[2], q3 = pbuf[3];
        const float UA = (q0.x + q1.x) + (q2.x + q3.x);
        const float UB = (q0.y + q1.y) + (q2.y + q3.y);
        g_total[bA] = (accA + lg2f(UA)) * LN2;
        g_total[bB] = (accB + lg2f(UB)) * LN2;
    }
}

// Real path score per batch: emission gather + transition chain.
__global__ void real_kernel(const float* __restrict__ emis,
                            const int* __restrict__ labels,
                            const float* __restrict__ trans) {
    const int b = blockIdx.x;
    const int tid = threadIdx.x;  // 128 threads
    const int*   lab = labels + (size_t)b * TT;
    const float* eb  = emis + (size_t)b * TT * LBL;

    float acc = 0.f;
    for (int t = tid; t < TT; t += 128) {
        const int l = lab[t];
        acc += eb[(size_t)t * LBL + l];
        const int prev = (t == 0) ? LBL : lab[t - 1];
        acc += trans[prev * NS + l];
    }
    if (tid == 0) acc += trans[lab[TT - 1] * NS + (LBL + 1)];  // last -> END

    __shared__ float rr[4];
    #pragma unroll
    for (int o = 16; o > 0; o >>= 1) acc += __shfl_xor_sync(0xffffffffu, acc, o);
    if ((tid & 31) == 0) rr[tid >> 5] = acc;
    __syncthreads();
    if (tid == 0) g_real[b] = (rr[0] + rr[1]) + (rr[2] + rr[3]);
}

// Deterministic final sum over batches.
__global__ void final_kernel(float* __restrict__ out) {
    const int b = threadIdx.x;  // 512 threads
    float v = g_total[b] - g_real[b];
    __shared__ float rr[16];
    #pragma unroll
    for (int o = 16; o > 0; o >>= 1) v += __shfl_xor_sync(0xffffffffu, v, o);
    if ((b & 31) == 0) rr[b >> 5] = v;
    __syncthreads();
    if (b < 16) {
        float x = rr[b];
        #pragma unroll
        for (int o = 8; o > 0; o >>= 1) x += __shfl_xor_sync(0x0000ffffu, x, o);
        if (b == 0) out[0] = x;
    }
}

extern "C" void kernel_launch(void* const* d_in, const int* in_sizes, int n_in,
                              void* d_out, int out_size) {
    const float* emis   = (const float*)d_in[0];
    const int*   labels = (const int*)d_in[1];
    const float* trans  = (const float*)d_in[2];
    float*       out    = (float*)d_out;

    // VT + 2 groups x (2 u-buffers of 256 floats) + red (2g x 8 float2) + mref (2g x 2 float2)
    const size_t smem = (NS * STRIDE + 1024 + 32 + 16) * sizeof(float);
    cudaFuncSetAttribute(main_kernel, cudaFuncAttributeMaxDynamicSharedMemorySize, (int)smem);

    prep_kernel<<<(NS * NS + 255) / 256, 256>>>(trans);
    main_kernel<<<BB / 4, NTHR, smem>>>(emis);
    real_kernel<<<BB, 128>>>(emis, labels, trans);
    final_kernel<<<1, BB>>>(out);
}